// round 6
// baseline (speedup 1.0000x reference)
#include <cuda_runtime.h>

#define NN      20000
#define IN_DIM  64
#define H       32
#define E_EDGES 200000
#define ED      8
#define EH      32
#define H2      1024   // H*H
#define CAP     64     // per-src bucket capacity (Poisson(10): P(deg>40) ~ 0)

// ---------------- device scratch ----------------
__device__ float g_xemb[NN * H];
__device__ float g_nb[NN * H];
__device__ float g_Wp[H * H2];                  // Wp[h][o*32+k] = We2[k][h*32+o]
__device__ float g_h1[(size_t)E_EDGES * EH];    // 25.6 MB per-edge hidden
__device__ int   g_cnt[NN];
__device__ int2  g_pair[NN * CAP];              // (edge id, dst)
__device__ float g_agg[NN * H];

// ---------------- K1: embed + nb + Wp permute + zero cnt ----------------
__global__ __launch_bounds__(256) void k_embed(const float* __restrict__ x,
                                               const float* __restrict__ W0,
                                               const float* __restrict__ b0,
                                               const float* __restrict__ be2,
                                               const float* __restrict__ We2) {
    __shared__ float W0s[IN_DIM * H];
    __shared__ float be2s[H2];
    __shared__ float xrow[8][IN_DIM];
    int tid = threadIdx.x;
    for (int i = tid; i < IN_DIM * H; i += 256) W0s[i] = W0[i];
    for (int i = tid; i < H2; i += 256)         be2s[i] = be2[i];

    int g = blockIdx.x * 256 + tid;             // 0..639999
    if (g < NN) g_cnt[g] = 0;
    if (g < H * H2) {                           // permute We2 -> Wp
        float v = We2[g];                       // g = k*1024 + h*32 + o
        int k = g >> 10, h = (g >> 5) & 31, o = g & 31;
        g_Wp[h * H2 + o * H + k] = v;
    }

    int w = tid >> 5, lane = tid & 31;
    int n = blockIdx.x * 8 + w;
    xrow[w][lane]      = x[n * IN_DIM + lane];
    xrow[w][lane + 32] = x[n * IN_DIM + 32 + lane];
    __syncthreads();

    float acc = b0[lane];
#pragma unroll
    for (int i = 0; i < IN_DIM; i++) acc += xrow[w][i] * W0s[i * H + lane];
    float xe = fmaxf(acc, 0.0f);
    g_xemb[n * H + lane] = xe;

    float nb = 0.0f;
#pragma unroll
    for (int h = 0; h < H; h++) {
        float xh = __shfl_sync(0xffffffffu, xe, h);
        nb += xh * be2s[h * H + lane];
    }
    g_nb[n * H + lane] = nb;
}

// ---------------- K2: build — warp per 8 edges, lane = k ----------------
__global__ __launch_bounds__(256) void k_build(const float* __restrict__ edge_attr,
                                               const float* __restrict__ We1,
                                               const float* __restrict__ be1,
                                               const int* __restrict__ ei) {
    __shared__ float W1s[ED * EH];
    __shared__ float b1s[EH];
    __shared__ float eas[8][64];
    int tid = threadIdx.x;
    if (tid < ED * EH) W1s[tid] = We1[tid];
    if (tid < EH)      b1s[tid] = be1[tid];
    __syncthreads();

    int w = tid >> 5, lane = tid & 31;
    int we = blockIdx.x * 8 + w;                // warp-edge-group, 25000 total
    int e0 = we * 8;

    float2 ea2 = ((const float2*)edge_attr)[we * 32 + lane];   // coalesced
    eas[w][lane * 2]     = ea2.x;
    eas[w][lane * 2 + 1] = ea2.y;
    __syncwarp();

    float acc[8];
#pragma unroll
    for (int e = 0; e < 8; e++) acc[e] = b1s[lane];
#pragma unroll
    for (int d = 0; d < ED; d++) {
        float wv = W1s[d * EH + lane];
#pragma unroll
        for (int e = 0; e < 8; e++) acc[e] += eas[w][e * 8 + d] * wv;
    }
#pragma unroll
    for (int e = 0; e < 8; e++)
        g_h1[(size_t)(e0 + e) * EH + lane] = fmaxf(acc[e], 0.0f);   // coalesced

    if (lane < 8) {
        int e = e0 + lane;
        int s = ei[e];
        int d = ei[E_EDGES + e];
        if ((unsigned)s < NN && (unsigned)d < NN) {
            int p = atomicAdd(&g_cnt[s], 1);
            if (p < CAP) g_pair[s * CAP + p] = make_int2(e, d);
        }
    }
}

// ---------------- K3: zero agg (also places k_msg in profiled slot 4) ----------------
__global__ void k_zero() {
    int g = blockIdx.x * 1024 + threadIdx.x;
    if (g < NN * H) g_agg[g] = 0.0f;
}

// ---------------- K4: FUSED messages — warp per src node ----------------
// Tf built in registers from smem-resident Wp; no g_T, no DRAM round trip.
#define NGRP (NN / 16)   // 1250 node-groups of 16 (one per warp)
__global__ __launch_bounds__(512) void k_msg() {
    extern __shared__ float Wps[];              // 32768 floats = 128 KB
    int tid = threadIdx.x;
    for (int i = tid; i < (H * H2) / 4; i += 512)
        ((float4*)Wps)[i] = ((const float4*)g_Wp)[i];
    __syncthreads();

    int w = tid >> 5, lane = tid & 31;

    for (int grp = blockIdx.x; grp < NGRP; grp += gridDim.x) {
        int n = grp * 16 + w;
        int deg = g_cnt[n];
        if (deg > CAP) deg = CAP;
        if (deg == 0) continue;

        float xe  = g_xemb[n * H + lane];
        float nbv = g_nb[n * H + lane];

        // Build Tf: lane = o; Tp[2i] = {Tf[4i],Tf[4i+1]}, Tp[2i+1] = {Tf[4i+2],Tf[4i+3]}
        unsigned long long Tp[16];
#pragma unroll
        for (int i = 0; i < 16; i++) Tp[i] = 0ull;

#pragma unroll
        for (int h = 0; h < H; h++) {
            float xh = __shfl_sync(0xffffffffu, xe, h);
            if (xh != 0.0f) {                   // warp-uniform ReLU skip (~50%)
                unsigned long long xd;
                asm("mov.b64 %0, {%1, %1};" : "=l"(xd) : "r"(__float_as_uint(xh)));
                const ulonglong2* p = (const ulonglong2*)(Wps + h * H2 + lane * 32);
#pragma unroll
                for (int i = 0; i < 8; i++) {
                    ulonglong2 v = p[i];        // LDS.128: two packed f32x2 operands
                    asm("fma.rn.f32x2 %0, %1, %2, %0;" : "+l"(Tp[2*i])   : "l"(xd), "l"(v.x));
                    asm("fma.rn.f32x2 %0, %1, %2, %0;" : "+l"(Tp[2*i+1]) : "l"(xd), "l"(v.y));
                }
            }
        }

        // Edge loop: batches of 32 pairs prefetched across lanes
        for (int j0 = 0; j0 < deg; j0 += 32) {
            int idx = j0 + lane;
            if (idx >= deg) idx = deg - 1;
            int2 myp = g_pair[n * CAP + idx];
            int jn = deg - j0; if (jn > 32) jn = 32;

            for (int j = 0; j < jn; j++) {
                int e = __shfl_sync(0xffffffffu, myp.x, j);
                int d = __shfl_sync(0xffffffffu, myp.y, j);
                const ulonglong2* hp = (const ulonglong2*)(g_h1 + (size_t)e * EH);
                unsigned long long acc = 0ull;
#pragma unroll
                for (int i = 0; i < 8; i++) {
                    ulonglong2 hv = hp[i];      // broadcast LDG.128, L2-hot
                    asm("fma.rn.f32x2 %0, %1, %2, %0;" : "+l"(acc) : "l"(hv.x), "l"(Tp[2*i]));
                    asm("fma.rn.f32x2 %0, %1, %2, %0;" : "+l"(acc) : "l"(hv.y), "l"(Tp[2*i+1]));
                }
                unsigned lo, hi;
                asm("mov.b64 {%0, %1}, %2;" : "=r"(lo), "=r"(hi) : "l"(acc));
                float msg = nbv + __uint_as_float(lo) + __uint_as_float(hi);
                atomicAdd(&g_agg[d * H + lane], msg);   // coalesced RED, spread addrs
            }
        }
    }
}

// ---------------- K5: root + GRU ----------------
__global__ __launch_bounds__(256) void k_final(const float* __restrict__ root,
                                               const float* __restrict__ bconv,
                                               const float* __restrict__ w_ih,
                                               const float* __restrict__ w_hh,
                                               const float* __restrict__ b_ih,
                                               const float* __restrict__ b_hh,
                                               float* __restrict__ out) {
    __shared__ float roots[H * H];
    __shared__ float wihT[H * 96];
    __shared__ float whhT[H * 96];
    __shared__ float bihs[96], bhhs[96], bconvs[H];
    int tid = threadIdx.x;
    for (int i = tid; i < H * H; i += 256) roots[i] = root[i];
    for (int i = tid; i < H * 96; i += 256) {
        int h = i / 96, j = i - h * 96;
        wihT[i] = w_ih[j * H + h];
        whhT[i] = w_hh[j * H + h];
    }
    if (tid < 96) { bihs[tid] = b_ih[tid]; bhhs[tid] = b_hh[tid]; }
    if (tid < H)  bconvs[tid] = bconv[tid];
    __syncthreads();

    int lane = tid & 31;
    int n = (blockIdx.x * 256 + tid) >> 5;

    float xe = g_xemb[n * H + lane];
    float conv = g_agg[n * H + lane] + bconvs[lane];
#pragma unroll
    for (int h = 0; h < H; h++) {
        float xh = __shfl_sync(0xffffffffu, xe, h);
        conv += xh * roots[h * H + lane];
    }

    float ar = bihs[lane], az = bihs[32 + lane], an = bihs[64 + lane];
    float hr = bhhs[lane], hz = bhhs[32 + lane], hn = bhhs[64 + lane];
#pragma unroll
    for (int h = 0; h < H; h++) {
        float ch = __shfl_sync(0xffffffffu, conv, h);
        float xh = __shfl_sync(0xffffffffu, xe, h);
        const float* wi = &wihT[h * 96];
        const float* wh = &whhT[h * 96];
        ar += ch * wi[lane];      az += ch * wi[32 + lane];  an += ch * wi[64 + lane];
        hr += xh * wh[lane];      hz += xh * wh[32 + lane];  hn += xh * wh[64 + lane];
    }

    float r  = 1.0f / (1.0f + expf(-(ar + hr)));
    float z  = 1.0f / (1.0f + expf(-(az + hz)));
    float nn = tanhf(an + r * hn);
    out[n * H + lane] = (1.0f - z) * nn + z * xe;
}

// ---------------- launcher ----------------
extern "C" void kernel_launch(void* const* d_in, const int* in_sizes, int n_in,
                              void* d_out, int out_size) {
    const float* x         = (const float*)d_in[0];
    const float* edge_attr = (const float*)d_in[1];
    const float* W0        = (const float*)d_in[2];
    const float* b0        = (const float*)d_in[3];
    const float* We1       = (const float*)d_in[4];
    const float* be1       = (const float*)d_in[5];
    const float* We2       = (const float*)d_in[6];
    const float* be2       = (const float*)d_in[7];
    const float* root      = (const float*)d_in[8];
    const float* bconv     = (const float*)d_in[9];
    const float* w_ih      = (const float*)d_in[10];
    const float* w_hh      = (const float*)d_in[11];
    const float* b_ih      = (const float*)d_in[12];
    const float* b_hh      = (const float*)d_in[13];
    const int*   ei        = (const int*)d_in[14];
    float* out = (float*)d_out;

    size_t smem_msg = (size_t)(H * H2) * sizeof(float);   // 131072 B
    cudaFuncSetAttribute(k_msg, cudaFuncAttributeMaxDynamicSharedMemorySize, (int)smem_msg);

    k_embed<<<NN * H / 256, 256>>>(x, W0, b0, be2, We2);       // 1
    k_build<<<E_EDGES / 64, 256>>>(edge_attr, We1, be1, ei);   // 2
    k_zero <<<(NN * H + 1023) / 1024, 1024>>>();               // 3
    k_msg  <<<148, 512, smem_msg>>>();                         // 4  <- profiled slot
    k_final<<<NN / 8, 256>>>(root, bconv, w_ih, w_hh, b_ih, b_hh, out);  // 5
}

// round 7
// speedup vs baseline: 2.3772x; 2.3772x over previous
#include <cuda_runtime.h>

#define NN      20000
#define IN_DIM  64
#define H       32
#define E_EDGES 200000
#define ED      8
#define EH      32
#define H2      1024   // H*H
#define CAP     64     // per-src bucket capacity (Poisson(10): P(deg>40) ~ 0)

// ---------------- device scratch ----------------
__device__ float g_xemb[NN * H];
__device__ float g_nb[NN * H];
__device__ float g_Wp[H * H2];                  // k-group-major: [h][k/4][o][k%4]
__device__ float g_h1[(size_t)E_EDGES * EH];    // 25.6 MB per-edge hidden
__device__ int   g_cnt[NN];
__device__ int2  g_pair[NN * CAP];              // (edge id, dst)
__device__ float g_agg[NN * H];

// ---------------- K1: embed + nb + Wp permute + zero cnt ----------------
__global__ __launch_bounds__(256) void k_embed(const float* __restrict__ x,
                                               const float* __restrict__ W0,
                                               const float* __restrict__ b0,
                                               const float* __restrict__ be2,
                                               const float* __restrict__ We2) {
    __shared__ float W0s[IN_DIM * H];
    __shared__ float be2s[H2];
    __shared__ float xrow[8][IN_DIM];
    int tid = threadIdx.x;
    for (int i = tid; i < IN_DIM * H; i += 256) W0s[i] = W0[i];
    for (int i = tid; i < H2; i += 256)         be2s[i] = be2[i];

    int g = blockIdx.x * 256 + tid;             // 0..639999
    if (g < NN) g_cnt[g] = 0;
    if (g < H * H2) {
        // We2[k][h*32+o] -> Wp[h*1024 + (k/4)*128 + o*4 + (k%4)]  (k-group-major)
        float v = We2[g];                       // g = k*1024 + h*32 + o
        int k = g >> 10, h = (g >> 5) & 31, o = g & 31;
        g_Wp[h * H2 + (k >> 2) * 128 + o * 4 + (k & 3)] = v;
    }

    int w = tid >> 5, lane = tid & 31;
    int n = blockIdx.x * 8 + w;
    xrow[w][lane]      = x[n * IN_DIM + lane];
    xrow[w][lane + 32] = x[n * IN_DIM + 32 + lane];
    __syncthreads();

    float acc = b0[lane];
#pragma unroll
    for (int i = 0; i < IN_DIM; i++) acc += xrow[w][i] * W0s[i * H + lane];
    float xe = fmaxf(acc, 0.0f);
    g_xemb[n * H + lane] = xe;

    float nb = 0.0f;
#pragma unroll
    for (int h = 0; h < H; h++) {
        float xh = __shfl_sync(0xffffffffu, xe, h);
        nb += xh * be2s[h * H + lane];
    }
    g_nb[n * H + lane] = nb;
}

// ---------------- K2: build — warp per 8 edges, lane = k ----------------
__global__ __launch_bounds__(256) void k_build(const float* __restrict__ edge_attr,
                                               const float* __restrict__ We1,
                                               const float* __restrict__ be1,
                                               const int* __restrict__ ei) {
    __shared__ float W1s[ED * EH];
    __shared__ float b1s[EH];
    __shared__ float eas[8][64];
    int tid = threadIdx.x;
    if (tid < ED * EH) W1s[tid] = We1[tid];
    if (tid < EH)      b1s[tid] = be1[tid];
    __syncthreads();

    int w = tid >> 5, lane = tid & 31;
    int we = blockIdx.x * 8 + w;                // 25000 warp-edge-groups
    int e0 = we * 8;

    float2 ea2 = ((const float2*)edge_attr)[we * 32 + lane];   // coalesced
    eas[w][lane * 2]     = ea2.x;
    eas[w][lane * 2 + 1] = ea2.y;
    __syncwarp();

    float acc[8];
#pragma unroll
    for (int e = 0; e < 8; e++) acc[e] = b1s[lane];
#pragma unroll
    for (int d = 0; d < ED; d++) {
        float wv = W1s[d * EH + lane];
#pragma unroll
        for (int e = 0; e < 8; e++) acc[e] += eas[w][e * 8 + d] * wv;
    }
#pragma unroll
    for (int e = 0; e < 8; e++)
        g_h1[(size_t)(e0 + e) * EH + lane] = fmaxf(acc[e], 0.0f);   // coalesced

    if (lane < 8) {
        int e = e0 + lane;
        int s = ei[e];
        int d = ei[E_EDGES + e];
        if ((unsigned)s < NN && (unsigned)d < NN) {
            int p = atomicAdd(&g_cnt[s], 1);
            if (p < CAP) g_pair[s * CAP + p] = make_int2(e, d);
        }
    }
}

// ---------------- K3: zero agg ----------------
__global__ void k_zero() {
    int g = blockIdx.x * 1024 + threadIdx.x;
    if (g < NN * H) g_agg[g] = 0.0f;
}

// ---------------- K4: FUSED messages — warp per src node, conflict-free Wp ----------------
#define MSG_T 768
#define NWARPS (MSG_T / 32)                      // 24 warps/block
__global__ __launch_bounds__(MSG_T, 1) void k_msg() {
    extern __shared__ float Wps[];               // 32768 floats, k-group-major
    int tid = threadIdx.x;
    for (int i = tid; i < (H * H2) / 4; i += MSG_T)
        ((float4*)Wps)[i] = ((const float4*)g_Wp)[i];   // linear copy (layout premade)
    __syncthreads();

    int w = tid >> 5, lane = tid & 31;
    const int ngrp = (NN + NWARPS - 1) / NWARPS; // 834

    for (int grp = blockIdx.x; grp < ngrp; grp += gridDim.x) {
        int n = grp * NWARPS + w;
        if (n >= NN) continue;
        int deg = g_cnt[n];
        if (deg > CAP) deg = CAP;
        if (deg == 0) continue;

        float xe  = g_xemb[n * H + lane];
        float nbv = g_nb[n * H + lane];

        // Tf build: lane = o; slot i covers k = 4i..4i+3
        // read float4 at Wps[h*256 + i*32 + lane]: per 8-lane phase all 32 banks -> floor
        unsigned long long Tp[16];
#pragma unroll
        for (int i = 0; i < 16; i++) Tp[i] = 0ull;

#pragma unroll
        for (int h = 0; h < H; h++) {
            float xh = __shfl_sync(0xffffffffu, xe, h);
            if (xh != 0.0f) {                    // warp-uniform ReLU skip (~50%)
                unsigned long long xd;
                asm("mov.b64 %0, {%1, %1};" : "=l"(xd) : "r"(__float_as_uint(xh)));
                const ulonglong2* p = (const ulonglong2*)(Wps + h * H2) + lane;
#pragma unroll
                for (int i = 0; i < 8; i++) {
                    ulonglong2 v = p[i * 32];    // compile-time offsets, conflict-free
                    asm("fma.rn.f32x2 %0, %1, %2, %0;" : "+l"(Tp[2*i])   : "l"(xd), "l"(v.x));
                    asm("fma.rn.f32x2 %0, %1, %2, %0;" : "+l"(Tp[2*i+1]) : "l"(xd), "l"(v.y));
                }
            }
        }

        // Edge loop: batches of 32 pairs prefetched across lanes
        for (int j0 = 0; j0 < deg; j0 += 32) {
            int idx = j0 + lane;
            if (idx >= deg) idx = deg - 1;
            int2 myp = g_pair[n * CAP + idx];
            int jn = deg - j0; if (jn > 32) jn = 32;

            for (int j = 0; j < jn; j++) {
                int e = __shfl_sync(0xffffffffu, myp.x, j);
                int d = __shfl_sync(0xffffffffu, myp.y, j);
                const ulonglong2* hp = (const ulonglong2*)(g_h1 + (size_t)e * EH);
                unsigned long long acc = 0ull;
#pragma unroll
                for (int i = 0; i < 8; i++) {
                    ulonglong2 hv = hp[i];       // broadcast LDG.128, L2-hot
                    asm("fma.rn.f32x2 %0, %1, %2, %0;" : "+l"(acc) : "l"(hv.x), "l"(Tp[2*i]));
                    asm("fma.rn.f32x2 %0, %1, %2, %0;" : "+l"(acc) : "l"(hv.y), "l"(Tp[2*i+1]));
                }
                unsigned lo, hi;
                asm("mov.b64 {%0, %1}, %2;" : "=r"(lo), "=r"(hi) : "l"(acc));
                float msg = nbv + __uint_as_float(lo) + __uint_as_float(hi);
                atomicAdd(&g_agg[d * H + lane], msg);   // coalesced RED, spread addrs
            }
        }
    }
}

// ---------------- K5: root + GRU ----------------
__global__ __launch_bounds__(256) void k_final(const float* __restrict__ root,
                                               const float* __restrict__ bconv,
                                               const float* __restrict__ w_ih,
                                               const float* __restrict__ w_hh,
                                               const float* __restrict__ b_ih,
                                               const float* __restrict__ b_hh,
                                               float* __restrict__ out) {
    __shared__ float roots[H * H];
    __shared__ float wihT[H * 96];
    __shared__ float whhT[H * 96];
    __shared__ float bihs[96], bhhs[96], bconvs[H];
    int tid = threadIdx.x;
    for (int i = tid; i < H * H; i += 256) roots[i] = root[i];
    for (int i = tid; i < H * 96; i += 256) {
        int h = i / 96, j = i - h * 96;
        wihT[i] = w_ih[j * H + h];
        whhT[i] = w_hh[j * H + h];
    }
    if (tid < 96) { bihs[tid] = b_ih[tid]; bhhs[tid] = b_hh[tid]; }
    if (tid < H)  bconvs[tid] = bconv[tid];
    __syncthreads();

    int lane = tid & 31;
    int n = (blockIdx.x * 256 + tid) >> 5;

    float xe = g_xemb[n * H + lane];
    float conv = g_agg[n * H + lane] + bconvs[lane];
#pragma unroll
    for (int h = 0; h < H; h++) {
        float xh = __shfl_sync(0xffffffffu, xe, h);
        conv += xh * roots[h * H + lane];
    }

    float ar = bihs[lane], az = bihs[32 + lane], an = bihs[64 + lane];
    float hr = bhhs[lane], hz = bhhs[32 + lane], hn = bhhs[64 + lane];
#pragma unroll
    for (int h = 0; h < H; h++) {
        float ch = __shfl_sync(0xffffffffu, conv, h);
        float xh = __shfl_sync(0xffffffffu, xe, h);
        const float* wi = &wihT[h * 96];
        const float* wh = &whhT[h * 96];
        ar += ch * wi[lane];      az += ch * wi[32 + lane];  an += ch * wi[64 + lane];
        hr += xh * wh[lane];      hz += xh * wh[32 + lane];  hn += xh * wh[64 + lane];
    }

    float r  = 1.0f / (1.0f + expf(-(ar + hr)));
    float z  = 1.0f / (1.0f + expf(-(az + hz)));
    float nn = tanhf(an + r * hn);
    out[n * H + lane] = (1.0f - z) * nn + z * xe;
}

// ---------------- launcher ----------------
extern "C" void kernel_launch(void* const* d_in, const int* in_sizes, int n_in,
                              void* d_out, int out_size) {
    const float* x         = (const float*)d_in[0];
    const float* edge_attr = (const float*)d_in[1];
    const float* W0        = (const float*)d_in[2];
    const float* b0        = (const float*)d_in[3];
    const float* We1       = (const float*)d_in[4];
    const float* be1       = (const float*)d_in[5];
    const float* We2       = (const float*)d_in[6];
    const float* be2       = (const float*)d_in[7];
    const float* root      = (const float*)d_in[8];
    const float* bconv     = (const float*)d_in[9];
    const float* w_ih      = (const float*)d_in[10];
    const float* w_hh      = (const float*)d_in[11];
    const float* b_ih      = (const float*)d_in[12];
    const float* b_hh      = (const float*)d_in[13];
    const int*   ei        = (const int*)d_in[14];
    float* out = (float*)d_out;

    size_t smem_msg = (size_t)(H * H2) * sizeof(float);   // 131072 B
    cudaFuncSetAttribute(k_msg, cudaFuncAttributeMaxDynamicSharedMemorySize, (int)smem_msg);

    k_embed<<<NN * H / 256, 256>>>(x, W0, b0, be2, We2);       // 1
    k_build<<<E_EDGES / 64, 256>>>(edge_attr, We1, be1, ei);   // 2
    k_zero <<<(NN * H + 1023) / 1024, 1024>>>();               // 3
    k_msg  <<<148, MSG_T, smem_msg>>>();                       // 4  <- profiled slot
    k_final<<<NN / 8, 256>>>(root, bconv, w_ih, w_hh, b_ih, b_hh, out);  // 5
}

// round 8
// speedup vs baseline: 2.7162x; 1.1426x over previous
#include <cuda_runtime.h>

#define NN      20000
#define IN_DIM  64
#define H       32
#define E_EDGES 200000
#define ED      8
#define EH      32
#define H2      1024   // H*H
#define CAP     64     // per-node bucket capacity (Poisson(10): P(deg>64) ~ 0)

typedef unsigned long long u64;

// ---------------- device scratch ----------------
__device__ float g_xemb[NN * H];
__device__ float g_nb[NN * H];
__device__ float g_Wp[H * H2];                    // k-group-major: [h][k/4][o][k%4]
__device__ float g_h1[(size_t)E_EDGES * EH];      // 25.6 MB per-edge hidden
__device__ int   g_cnt[NN];                       // src degree
__device__ int   g_cnt_dst[NN];                   // dst degree
__device__ int2  g_pair[NN * CAP];                // per-src: (edge id, dst slot)
__device__ float g_msg[((size_t)NN * CAP + 1) * H];  // dst-slotted messages (+dump row)

// ---------------- K1: embed + nb + zero counters ----------------
__global__ __launch_bounds__(256) void k_embed(const float* __restrict__ x,
                                               const float* __restrict__ W0,
                                               const float* __restrict__ b0,
                                               const float* __restrict__ be2) {
    __shared__ float W0s[IN_DIM * H];
    __shared__ float be2s[H2];
    __shared__ float xrow[8][IN_DIM];
    int tid = threadIdx.x;
    for (int i = tid; i < IN_DIM * H; i += 256) W0s[i] = W0[i];
    for (int i = tid; i < H2; i += 256)         be2s[i] = be2[i];

    int g = blockIdx.x * 256 + tid;               // 0..639999
    if (g < NN)          g_cnt[g] = 0;
    else if (g < 2 * NN) g_cnt_dst[g - NN] = 0;

    int w = tid >> 5, lane = tid & 31;
    int n = blockIdx.x * 8 + w;
    xrow[w][lane]      = x[n * IN_DIM + lane];
    xrow[w][lane + 32] = x[n * IN_DIM + 32 + lane];
    __syncthreads();

    float acc = b0[lane];
#pragma unroll
    for (int i = 0; i < IN_DIM; i++) acc += xrow[w][i] * W0s[i * H + lane];
    float xe = fmaxf(acc, 0.0f);
    g_xemb[n * H + lane] = xe;

    float nb = 0.0f;
#pragma unroll
    for (int h = 0; h < H; h++) {
        float xh = __shfl_sync(0xffffffffu, xe, h);
        nb += xh * be2s[h * H + lane];
    }
    g_nb[n * H + lane] = nb;
}

// ---------------- K2: build — warp per 8 edges; src + dst slot assignment ----------------
__global__ __launch_bounds__(256) void k_build(const float* __restrict__ edge_attr,
                                               const float* __restrict__ We1,
                                               const float* __restrict__ be1,
                                               const int* __restrict__ ei) {
    __shared__ float W1s[ED * EH];
    __shared__ float b1s[EH];
    __shared__ float eas[8][64];
    int tid = threadIdx.x;
    if (tid < ED * EH) W1s[tid] = We1[tid];
    if (tid < EH)      b1s[tid] = be1[tid];
    __syncthreads();

    int w = tid >> 5, lane = tid & 31;
    int we = blockIdx.x * 8 + w;                  // 25000 warp-edge-groups
    int e0 = we * 8;

    float2 ea2 = ((const float2*)edge_attr)[we * 32 + lane];
    eas[w][lane * 2]     = ea2.x;
    eas[w][lane * 2 + 1] = ea2.y;
    __syncwarp();

    float acc[8];
#pragma unroll
    for (int e = 0; e < 8; e++) acc[e] = b1s[lane];
#pragma unroll
    for (int d = 0; d < ED; d++) {
        float wv = W1s[d * EH + lane];
#pragma unroll
        for (int e = 0; e < 8; e++) acc[e] += eas[w][e * 8 + d] * wv;
    }
#pragma unroll
    for (int e = 0; e < 8; e++)
        g_h1[(size_t)(e0 + e) * EH + lane] = fmaxf(acc[e], 0.0f);

    if (lane < 8) {
        int e = e0 + lane;
        int s = ei[e];
        int d = ei[E_EDGES + e];
        if ((unsigned)s < NN && (unsigned)d < NN) {
            int p = atomicAdd(&g_cnt[s], 1);
            int q = atomicAdd(&g_cnt_dst[d], 1);
            if (p < CAP) {
                int slot = (q < CAP) ? d * CAP + q : NN * CAP;   // dump row if overflow
                g_pair[s * CAP + p] = make_int2(e, slot);
            }
        }
    }
}

// ---------------- K3: permute We2 -> Wp (k-group-major) ----------------
__global__ void k_prep(const float* __restrict__ We2) {
    int g = blockIdx.x * 256 + threadIdx.x;       // 32768
    if (g < H * H2) {
        float v = We2[g];                         // g = k*1024 + h*32 + o
        int k = g >> 10, h = (g >> 5) & 31, o = g & 31;
        g_Wp[h * H2 + (k >> 2) * 128 + o * 4 + (k & 3)] = v;
    }
}

// ---------------- edge contraction (inlined; Tp const-indexed -> registers) ----------------
__device__ __forceinline__ void edge_loop(int n, int deg, const u64* Tp, int lane) {
    if (deg == 0) return;
    float nbv = g_nb[n * H + lane];
    const int2* pb = &g_pair[n * CAP];
#pragma unroll 2
    for (int j = 0; j < deg; j++) {
        int2 p = pb[j];                           // uniform LDG, L1-hot
        const ulonglong2* hp = (const ulonglong2*)(g_h1 + (size_t)p.x * EH);
        ulonglong2 hv[8];
#pragma unroll
        for (int i = 0; i < 8; i++) hv[i] = hp[i];   // batched broadcast LDG.128
        u64 a0 = 0ull, a1 = 0ull, a2 = 0ull, a3 = 0ull;
#pragma unroll
        for (int i = 0; i < 4; i++) {             // 4 independent chains, depth 4
            asm("fma.rn.f32x2 %0, %1, %2, %0;" : "+l"(a0) : "l"(hv[2*i].x),   "l"(Tp[4*i]));
            asm("fma.rn.f32x2 %0, %1, %2, %0;" : "+l"(a1) : "l"(hv[2*i].y),   "l"(Tp[4*i+1]));
            asm("fma.rn.f32x2 %0, %1, %2, %0;" : "+l"(a2) : "l"(hv[2*i+1].x), "l"(Tp[4*i+2]));
            asm("fma.rn.f32x2 %0, %1, %2, %0;" : "+l"(a3) : "l"(hv[2*i+1].y), "l"(Tp[4*i+3]));
        }
        asm("add.rn.f32x2 %0, %0, %1;" : "+l"(a0) : "l"(a1));
        asm("add.rn.f32x2 %0, %0, %1;" : "+l"(a2) : "l"(a3));
        asm("add.rn.f32x2 %0, %0, %1;" : "+l"(a0) : "l"(a2));
        unsigned lo, hi;
        asm("mov.b64 {%0, %1}, %2;" : "=r"(lo), "=r"(hi) : "l"(a0));
        g_msg[(size_t)p.y * H + lane] = nbv + __uint_as_float(lo) + __uint_as_float(hi);
    }
}

// ---------------- K4: FUSED messages — 2 nodes per warp, slot stores ----------------
#define MSG_T 512
__global__ __launch_bounds__(MSG_T, 1) void k_msg() {
    extern __shared__ float Wps[];                // 32768 floats, k-group-major
    int tid = threadIdx.x;
    for (int i = tid; i < (H * H2) / 4; i += MSG_T)
        ((float4*)Wps)[i] = ((const float4*)g_Wp)[i];
    __syncthreads();

    int w = tid >> 5, lane = tid & 31;
    const int ngrp = NN / 32;                     // 625 groups of 32 nodes (16 warps x 2)

    for (int grp = blockIdx.x; grp < ngrp; grp += gridDim.x) {
        int nA = grp * 32 + w * 2;
        int nB = nA + 1;
        int dA = g_cnt[nA]; if (dA > CAP) dA = CAP;
        int dB = g_cnt[nB]; if (dB > CAP) dB = CAP;
        if ((dA | dB) == 0) continue;

        float xeA = g_xemb[nA * H + lane];
        float xeB = g_xemb[nB * H + lane];

        u64 TpA[16], TpB[16];
#pragma unroll
        for (int i = 0; i < 16; i++) { TpA[i] = 0ull; TpB[i] = 0ull; }

#pragma unroll
        for (int h = 0; h < H; h++) {
            float xa = __shfl_sync(0xffffffffu, xeA, h);
            float xb = __shfl_sync(0xffffffffu, xeB, h);
            if (xa != 0.0f || xb != 0.0f) {       // warp-uniform; one LDS stream, 2 nodes
                u64 xda, xdb;
                asm("mov.b64 %0, {%1, %1};" : "=l"(xda) : "r"(__float_as_uint(xa)));
                asm("mov.b64 %0, {%1, %1};" : "=l"(xdb) : "r"(__float_as_uint(xb)));
                const ulonglong2* p = (const ulonglong2*)(Wps + h * H2) + lane;
#pragma unroll
                for (int i = 0; i < 8; i++) {
                    ulonglong2 v = p[i * 32];     // conflict-free LDS.128
                    asm("fma.rn.f32x2 %0, %1, %2, %0;" : "+l"(TpA[2*i])   : "l"(xda), "l"(v.x));
                    asm("fma.rn.f32x2 %0, %1, %2, %0;" : "+l"(TpA[2*i+1]) : "l"(xda), "l"(v.y));
                    asm("fma.rn.f32x2 %0, %1, %2, %0;" : "+l"(TpB[2*i])   : "l"(xdb), "l"(v.x));
                    asm("fma.rn.f32x2 %0, %1, %2, %0;" : "+l"(TpB[2*i+1]) : "l"(xdb), "l"(v.y));
                }
            }
        }

        edge_loop(nA, dA, TpA, lane);
        edge_loop(nB, dB, TpB, lane);
    }
}

// ---------------- K5: slot gather + root + GRU (block-batched weights) ----------------
__global__ __launch_bounds__(256) void k_final(const float* __restrict__ root,
                                               const float* __restrict__ bconv,
                                               const float* __restrict__ w_ih,
                                               const float* __restrict__ w_hh,
                                               const float* __restrict__ b_ih,
                                               const float* __restrict__ b_hh,
                                               float* __restrict__ out) {
    __shared__ float roots[H * H];
    __shared__ float wihT[H * 96];
    __shared__ float whhT[H * 96];
    __shared__ float bihs[96], bhhs[96], bconvs[H];
    int tid = threadIdx.x;
    for (int i = tid; i < H * H; i += 256) roots[i] = root[i];
    for (int i = tid; i < H * 96; i += 256) {
        int h = i / 96, j = i - h * 96;
        wihT[i] = w_ih[j * H + h];
        whhT[i] = w_hh[j * H + h];
    }
    if (tid < 96) { bihs[tid] = b_ih[tid]; bhhs[tid] = b_hh[tid]; }
    if (tid < H)  bconvs[tid] = bconv[tid];
    __syncthreads();

    int lane = tid & 31, w = tid >> 5;

    for (int it = 0; it < 10; it++) {             // 250 blocks x 10 x 8 nodes = 20000
        int n = blockIdx.x * 80 + it * 8 + w;

        int deg = g_cnt_dst[n];
        if (deg > CAP) deg = CAP;
        float s = 0.0f;
        const float* mp = g_msg + (size_t)n * CAP * H + lane;
        for (int j = 0; j < deg; j++) s += mp[j * H];

        float xe = g_xemb[n * H + lane];
        float conv = s + bconvs[lane];
#pragma unroll
        for (int h = 0; h < H; h++) {
            float xh = __shfl_sync(0xffffffffu, xe, h);
            conv += xh * roots[h * H + lane];
        }

        float ar = bihs[lane], az = bihs[32 + lane], an = bihs[64 + lane];
        float hr = bhhs[lane], hz = bhhs[32 + lane], hn = bhhs[64 + lane];
#pragma unroll
        for (int h = 0; h < H; h++) {
            float ch = __shfl_sync(0xffffffffu, conv, h);
            float xh = __shfl_sync(0xffffffffu, xe, h);
            const float* wi = &wihT[h * 96];
            const float* wh = &whhT[h * 96];
            ar += ch * wi[lane];      az += ch * wi[32 + lane];  an += ch * wi[64 + lane];
            hr += xh * wh[lane];      hz += xh * wh[32 + lane];  hn += xh * wh[64 + lane];
        }

        float r  = 1.0f / (1.0f + expf(-(ar + hr)));
        float z  = 1.0f / (1.0f + expf(-(az + hz)));
        float nn = tanhf(an + r * hn);
        out[n * H + lane] = (1.0f - z) * nn + z * xe;
    }
}

// ---------------- launcher ----------------
extern "C" void kernel_launch(void* const* d_in, const int* in_sizes, int n_in,
                              void* d_out, int out_size) {
    const float* x         = (const float*)d_in[0];
    const float* edge_attr = (const float*)d_in[1];
    const float* W0        = (const float*)d_in[2];
    const float* b0        = (const float*)d_in[3];
    const float* We1       = (const float*)d_in[4];
    const float* be1       = (const float*)d_in[5];
    const float* We2       = (const float*)d_in[6];
    const float* be2       = (const float*)d_in[7];
    const float* root      = (const float*)d_in[8];
    const float* bconv     = (const float*)d_in[9];
    const float* w_ih      = (const float*)d_in[10];
    const float* w_hh      = (const float*)d_in[11];
    const float* b_ih      = (const float*)d_in[12];
    const float* b_hh      = (const float*)d_in[13];
    const int*   ei        = (const int*)d_in[14];
    float* out = (float*)d_out;

    size_t smem_msg = (size_t)(H * H2) * sizeof(float);   // 131072 B
    cudaFuncSetAttribute(k_msg, cudaFuncAttributeMaxDynamicSharedMemorySize, (int)smem_msg);

    k_embed<<<NN * H / 256, 256>>>(x, W0, b0, be2);            // 1
    k_build<<<E_EDGES / 64, 256>>>(edge_attr, We1, be1, ei);   // 2
    k_prep <<<H * H2 / 256, 256>>>(We2);                       // 3
    k_msg  <<<148, MSG_T, smem_msg>>>();                       // 4  <- profiled slot
    k_final<<<250, 256>>>(root, bconv, w_ih, w_hh, b_ih, b_hh, out);  // 5
}

// round 9
// speedup vs baseline: 2.9533x; 1.0873x over previous
#include <cuda_runtime.h>

#define NN      20000
#define IN_DIM  64
#define H       32
#define E_EDGES 200000
#define ED      8
#define EH      32
#define H2      1024   // H*H
#define CAP     64     // per-node bucket capacity (Poisson(10): P(deg>64) ~ 0)

typedef unsigned long long u64;

// ---------------- device scratch ----------------
__device__ float g_xemb[NN * H];
__device__ float g_nb[NN * H];
__device__ float g_Wp[H * H2];                    // k-group-major: [h][k/4][o][k%4]
__device__ float g_h1[(size_t)E_EDGES * EH];      // 25.6 MB per-edge hidden
__device__ int   g_cnt[NN];                       // src degree
__device__ int   g_cnt_dst[NN];                   // dst degree
__device__ int2  g_pair[NN * CAP];                // per-src: (edge id, dst slot)
__device__ float g_msg[((size_t)NN * CAP + 1) * H];  // dst-slotted messages (+dump row)

// ---------------- K1: embed + nb + zero counters ----------------
__global__ __launch_bounds__(256) void k_embed(const float* __restrict__ x,
                                               const float* __restrict__ W0,
                                               const float* __restrict__ b0,
                                               const float* __restrict__ be2) {
    __shared__ float W0s[IN_DIM * H];
    __shared__ float be2s[H2];
    __shared__ float xrow[8][IN_DIM];
    int tid = threadIdx.x;
    for (int i = tid; i < IN_DIM * H; i += 256) W0s[i] = W0[i];
    for (int i = tid; i < H2; i += 256)         be2s[i] = be2[i];

    int g = blockIdx.x * 256 + tid;               // 0..639999
    if (g < NN)          g_cnt[g] = 0;
    else if (g < 2 * NN) g_cnt_dst[g - NN] = 0;

    int w = tid >> 5, lane = tid & 31;
    int n = blockIdx.x * 8 + w;
    xrow[w][lane]      = x[n * IN_DIM + lane];
    xrow[w][lane + 32] = x[n * IN_DIM + 32 + lane];
    __syncthreads();

    float acc = b0[lane];
#pragma unroll
    for (int i = 0; i < IN_DIM; i++) acc += xrow[w][i] * W0s[i * H + lane];
    float xe = fmaxf(acc, 0.0f);
    g_xemb[n * H + lane] = xe;

    float nb = 0.0f;
#pragma unroll
    for (int h = 0; h < H; h++) {
        float xh = __shfl_sync(0xffffffffu, xe, h);
        nb += xh * be2s[h * H + lane];
    }
    g_nb[n * H + lane] = nb;
}

// ---------------- K2: build — warp per 8 edges; src + dst slot assignment ----------------
__global__ __launch_bounds__(256) void k_build(const float* __restrict__ edge_attr,
                                               const float* __restrict__ We1,
                                               const float* __restrict__ be1,
                                               const int* __restrict__ ei) {
    __shared__ float W1s[ED * EH];
    __shared__ float b1s[EH];
    __shared__ float eas[8][64];
    int tid = threadIdx.x;
    if (tid < ED * EH) W1s[tid] = We1[tid];
    if (tid < EH)      b1s[tid] = be1[tid];
    __syncthreads();

    int w = tid >> 5, lane = tid & 31;
    int we = blockIdx.x * 8 + w;                  // 25000 warp-edge-groups
    int e0 = we * 8;

    float2 ea2 = ((const float2*)edge_attr)[we * 32 + lane];
    eas[w][lane * 2]     = ea2.x;
    eas[w][lane * 2 + 1] = ea2.y;
    __syncwarp();

    float acc[8];
#pragma unroll
    for (int e = 0; e < 8; e++) acc[e] = b1s[lane];
#pragma unroll
    for (int d = 0; d < ED; d++) {
        float wv = W1s[d * EH + lane];
#pragma unroll
        for (int e = 0; e < 8; e++) acc[e] += eas[w][e * 8 + d] * wv;
    }
#pragma unroll
    for (int e = 0; e < 8; e++)
        g_h1[(size_t)(e0 + e) * EH + lane] = fmaxf(acc[e], 0.0f);

    if (lane < 8) {
        int e = e0 + lane;
        int s = ei[e];
        int d = ei[E_EDGES + e];
        if ((unsigned)s < NN && (unsigned)d < NN) {
            int p = atomicAdd(&g_cnt[s], 1);
            int q = atomicAdd(&g_cnt_dst[d], 1);
            if (p < CAP) {
                int slot = (q < CAP) ? d * CAP + q : NN * CAP;   // dump row if overflow
                g_pair[s * CAP + p] = make_int2(e, slot);
            }
        }
    }
}

// ---------------- K3: permute We2 -> Wp (k-group-major) ----------------
__global__ void k_prep(const float* __restrict__ We2) {
    int g = blockIdx.x * 256 + threadIdx.x;       // 32768
    if (g < H * H2) {
        float v = We2[g];                         // g = k*1024 + h*32 + o
        int k = g >> 10, h = (g >> 5) & 31, o = g & 31;
        g_Wp[h * H2 + (k >> 2) * 128 + o * 4 + (k & 3)] = v;
    }
}

// ---------------- K4: FUSED messages — 1 node/warp, 768 threads, slot stores ----------------
#define MSG_T 768
#define NWARPS (MSG_T / 32)                       // 24 warps/block
__global__ __launch_bounds__(MSG_T, 1) void k_msg() {
    extern __shared__ float Wps[];                // 32768 floats, k-group-major
    int tid = threadIdx.x;
    for (int i = tid; i < (H * H2) / 4; i += MSG_T)
        ((float4*)Wps)[i] = ((const float4*)g_Wp)[i];
    __syncthreads();

    int w = tid >> 5, lane = tid & 31;
    const int ngrp = (NN + NWARPS - 1) / NWARPS;  // 834

    for (int grp = blockIdx.x; grp < ngrp; grp += gridDim.x) {
        int n = grp * NWARPS + w;
        if (n >= NN) continue;
        int deg = g_cnt[n];
        if (deg > CAP) deg = CAP;
        if (deg == 0) continue;

        float xe  = g_xemb[n * H + lane];
        float nbv = g_nb[n * H + lane];

        // Tf build: lane = o; slot i covers k = 4i..4i+3 (conflict-free LDS.128)
        u64 Tp[16];
#pragma unroll
        for (int i = 0; i < 16; i++) Tp[i] = 0ull;

#pragma unroll
        for (int h = 0; h < H; h++) {
            float xh = __shfl_sync(0xffffffffu, xe, h);
            if (xh != 0.0f) {                     // warp-uniform ReLU skip (~50%)
                u64 xd;
                asm("mov.b64 %0, {%1, %1};" : "=l"(xd) : "r"(__float_as_uint(xh)));
                const ulonglong2* p = (const ulonglong2*)(Wps + h * H2) + lane;
#pragma unroll
                for (int i = 0; i < 8; i++) {
                    ulonglong2 v = p[i * 32];     // compile-time offsets, conflict-free
                    asm("fma.rn.f32x2 %0, %1, %2, %0;" : "+l"(Tp[2*i])   : "l"(xd), "l"(v.x));
                    asm("fma.rn.f32x2 %0, %1, %2, %0;" : "+l"(Tp[2*i+1]) : "l"(xd), "l"(v.y));
                }
            }
        }

        // Edge loop: slot stores, 4 independent FMA chains, batched h1 loads
        const int2* pb = &g_pair[n * CAP];
#pragma unroll 2
        for (int j = 0; j < deg; j++) {
            int2 p = pb[j];                       // uniform LDG, L1-hot
            const ulonglong2* hp = (const ulonglong2*)(g_h1 + (size_t)p.x * EH);
            ulonglong2 hv[8];
#pragma unroll
            for (int i = 0; i < 8; i++) hv[i] = hp[i];   // batched broadcast LDG.128
            u64 a0 = 0ull, a1 = 0ull, a2 = 0ull, a3 = 0ull;
#pragma unroll
            for (int i = 0; i < 4; i++) {         // 4 chains, depth 4
                asm("fma.rn.f32x2 %0, %1, %2, %0;" : "+l"(a0) : "l"(hv[2*i].x),   "l"(Tp[4*i]));
                asm("fma.rn.f32x2 %0, %1, %2, %0;" : "+l"(a1) : "l"(hv[2*i].y),   "l"(Tp[4*i+1]));
                asm("fma.rn.f32x2 %0, %1, %2, %0;" : "+l"(a2) : "l"(hv[2*i+1].x), "l"(Tp[4*i+2]));
                asm("fma.rn.f32x2 %0, %1, %2, %0;" : "+l"(a3) : "l"(hv[2*i+1].y), "l"(Tp[4*i+3]));
            }
            asm("add.rn.f32x2 %0, %0, %1;" : "+l"(a0) : "l"(a1));
            asm("add.rn.f32x2 %0, %0, %1;" : "+l"(a2) : "l"(a3));
            asm("add.rn.f32x2 %0, %0, %1;" : "+l"(a0) : "l"(a2));
            unsigned lo, hi;
            asm("mov.b64 {%0, %1}, %2;" : "=r"(lo), "=r"(hi) : "l"(a0));
            g_msg[(size_t)p.y * H + lane] = nbv + __uint_as_float(lo) + __uint_as_float(hi);
        }
    }
}

// ---------------- K5: slot gather + root + GRU (block-batched weights) ----------------
__global__ __launch_bounds__(256) void k_final(const float* __restrict__ root,
                                               const float* __restrict__ bconv,
                                               const float* __restrict__ w_ih,
                                               const float* __restrict__ w_hh,
                                               const float* __restrict__ b_ih,
                                               const float* __restrict__ b_hh,
                                               float* __restrict__ out) {
    __shared__ float roots[H * H];
    __shared__ float wihT[H * 96];
    __shared__ float whhT[H * 96];
    __shared__ float bihs[96], bhhs[96], bconvs[H];
    int tid = threadIdx.x;
    for (int i = tid; i < H * H; i += 256) roots[i] = root[i];
    for (int i = tid; i < H * 96; i += 256) {
        int h = i / 96, j = i - h * 96;
        wihT[i] = w_ih[j * H + h];
        whhT[i] = w_hh[j * H + h];
    }
    if (tid < 96) { bihs[tid] = b_ih[tid]; bhhs[tid] = b_hh[tid]; }
    if (tid < H)  bconvs[tid] = bconv[tid];
    __syncthreads();

    int lane = tid & 31, w = tid >> 5;

    for (int it = 0; it < 10; it++) {             // 250 blocks x 10 x 8 nodes = 20000
        int n = blockIdx.x * 80 + it * 8 + w;

        int deg = g_cnt_dst[n];
        if (deg > CAP) deg = CAP;
        float s = 0.0f;
        const float* mp = g_msg + (size_t)n * CAP * H + lane;
        for (int j = 0; j < deg; j++) s += mp[j * H];

        float xe = g_xemb[n * H + lane];
        float conv = s + bconvs[lane];
#pragma unroll
        for (int h = 0; h < H; h++) {
            float xh = __shfl_sync(0xffffffffu, xe, h);
            conv += xh * roots[h * H + lane];
        }

        float ar = bihs[lane], az = bihs[32 + lane], an = bihs[64 + lane];
        float hr = bhhs[lane], hz = bhhs[32 + lane], hn = bhhs[64 + lane];
#pragma unroll
        for (int h = 0; h < H; h++) {
            float ch = __shfl_sync(0xffffffffu, conv, h);
            float xh = __shfl_sync(0xffffffffu, xe, h);
            const float* wi = &wihT[h * 96];
            const float* wh = &whhT[h * 96];
            ar += ch * wi[lane];      az += ch * wi[32 + lane];  an += ch * wi[64 + lane];
            hr += xh * wh[lane];      hz += xh * wh[32 + lane];  hn += xh * wh[64 + lane];
        }

        float r  = 1.0f / (1.0f + expf(-(ar + hr)));
        float z  = 1.0f / (1.0f + expf(-(az + hz)));
        float nn = tanhf(an + r * hn);
        out[n * H + lane] = (1.0f - z) * nn + z * xe;
    }
}

// ---------------- launcher ----------------
extern "C" void kernel_launch(void* const* d_in, const int* in_sizes, int n_in,
                              void* d_out, int out_size) {
    const float* x         = (const float*)d_in[0];
    const float* edge_attr = (const float*)d_in[1];
    const float* W0        = (const float*)d_in[2];
    const float* b0        = (const float*)d_in[3];
    const float* We1       = (const float*)d_in[4];
    const float* be1       = (const float*)d_in[5];
    const float* We2       = (const float*)d_in[6];
    const float* be2       = (const float*)d_in[7];
    const float* root      = (const float*)d_in[8];
    const float* bconv     = (const float*)d_in[9];
    const float* w_ih      = (const float*)d_in[10];
    const float* w_hh      = (const float*)d_in[11];
    const float* b_ih      = (const float*)d_in[12];
    const float* b_hh      = (const float*)d_in[13];
    const int*   ei        = (const int*)d_in[14];
    float* out = (float*)d_out;

    size_t smem_msg = (size_t)(H * H2) * sizeof(float);   // 131072 B
    cudaFuncSetAttribute(k_msg, cudaFuncAttributeMaxDynamicSharedMemorySize, (int)smem_msg);

    k_embed<<<NN * H / 256, 256>>>(x, W0, b0, be2);            // 1
    k_build<<<E_EDGES / 64, 256>>>(edge_attr, We1, be1, ei);   // 2
    k_prep <<<H * H2 / 256, 256>>>(We2);                       // 3
    k_msg  <<<148, MSG_T, smem_msg>>>();                       // 4  <- profiled slot
    k_final<<<250, 256>>>(root, bconv, w_ih, w_hh, b_ih, b_hh, out);  // 5
}